// round 15
// baseline (speedup 1.0000x reference)
#include <cuda_runtime.h>
#include <cuda_fp16.h>
#include <cstdint>

// ============================================================================
// ModularLinear on GB300 — base-arch build. R13: single-term fp16 GEMM.
//   C = fp16(a) * fp16(b), fp32 accumulate.
// Error calibration from R12 (2-term, one dropped term = 1.85e-4): adding the
// second independent rounding term gives ~sqrt(2)*1.85e-4 ~ 2.6e-4 << 1e-3.
// MMA count is 1/3 of the original 3-term bf16 scheme. R8/R12 skeleton:
// TILE 128x128, KC=64, NSTG=4 (32KB stages), 384 thr (256 consumer + 128
// producer), warp-specialized ring, named barriers, early stage release.
//
//   out[t, b, kk*1024 + o] = sum_i x[t, b, i] * w[sel[b,kk], o, i]
//   16 independent GEMMs of 2048 x 1024 x 1024 (fp32).
// ============================================================================

#define T_DIM   2048
#define B_DIM   8
#define IN_DIM  1024
#define OUT_DIM 1024
#define K_SEL   2

#define TILE_M  128
#define TILE_N  128
#define KC      64                         // K-chunk (fp32 elements)
#define NCHUNK  (IN_DIM / KC)              // 16
#define THREADS 384                        // 256 consumer + 128 producer
#define NSTG    4

// fp16 tiles: 128 rows x 64 fp16 (128B rows), SW128-swizzled -> 16KB each
#define F_TILE      (TILE_M * KC * 2)      // 16384
#define OFF_AH      0
#define OFF_BH      F_TILE                 // 16384
#define STAGE_BYTES (2 * F_TILE)           // 32768
#define SMEM_TOTAL  (NSTG * STAGE_BYTES)   // 131072

// ---------------------------------------------------------------------------
// PTX helpers (base-arch only)
// ---------------------------------------------------------------------------
__device__ __forceinline__ uint32_t smem_u32(const void* p) {
    uint32_t a;
    asm("{ .reg .u64 t; cvta.to.shared.u64 t, %1; cvt.u32.u64 %0, t; }"
        : "=r"(a) : "l"(p));
    return a;
}

#define BAR_SYNC(id)   asm volatile("bar.sync %0, %1;"   :: "r"(id), "n"(THREADS) : "memory")
#define BAR_ARRIVE(id) asm volatile("bar.arrive %0, %1;" :: "r"(id), "n"(THREADS) : "memory")

__device__ __forceinline__ void ldsm4(uint32_t* r, uint32_t addr) {
    asm volatile("ldmatrix.sync.aligned.m8n8.x4.shared.b16 {%0,%1,%2,%3}, [%4];"
                 : "=r"(r[0]), "=r"(r[1]), "=r"(r[2]), "=r"(r[3])
                 : "r"(addr));
}

// D += A * B  (m16n8k16, fp16 in, fp32 acc)
__device__ __forceinline__ void mma16816(float* c, const uint32_t* a,
                                         const uint32_t* b) {
    asm volatile(
        "mma.sync.aligned.m16n8k16.row.col.f32.f16.f16.f32 "
        "{%0,%1,%2,%3}, {%4,%5,%6,%7}, {%8,%9}, {%0,%1,%2,%3};"
        : "+f"(c[0]), "+f"(c[1]), "+f"(c[2]), "+f"(c[3])
        : "r"(a[0]), "r"(a[1]), "r"(a[2]), "r"(a[3]),
          "r"(b[0]), "r"(b[1]));
}

// SW128 swizzle for 128B rows: bits[6:4] ^= bits[9:7]
__device__ __forceinline__ uint32_t sw128(uint32_t bo) {
    return bo ^ ((bo >> 3) & 0x70);
}

__device__ __forceinline__ uint32_t f2h2(float a, float b) {
    __half2 h = __floats2half2_rn(a, b);
    return *reinterpret_cast<uint32_t*>(&h);
}

// convert 8 fp32 (two uint4) to packed fp16 (one uint4)
__device__ __forceinline__ uint4 cvt_oct_f16(uint4 u0, uint4 u1) {
    uint4 hi;
    hi.x = f2h2(__uint_as_float(u0.x), __uint_as_float(u0.y));
    hi.y = f2h2(__uint_as_float(u0.z), __uint_as_float(u0.w));
    hi.z = f2h2(__uint_as_float(u1.x), __uint_as_float(u1.y));
    hi.w = f2h2(__uint_as_float(u1.z), __uint_as_float(u1.w));
    return hi;
}

// ============================================================================
// Kernel
// ============================================================================
__global__ void __launch_bounds__(THREADS, 1)
modlin_kernel(const float* __restrict__ x, const int* __restrict__ sel,
              const float* __restrict__ w, float* __restrict__ out)
{
    extern __shared__ char smem[];
    const int tid = threadIdx.x;
    const int wid = tid >> 5;
    const int lid = tid & 31;

    const int nt_blk = blockIdx.x;            // 0..7
    const int mt_blk = blockIdx.y;            // 0..15
    const int pi     = blockIdx.z;            // 0..15  (b,k) pair
    const int b  = pi >> 1;
    const int kk = pi & 1;
    const int m0 = mt_blk * TILE_M;
    const int n0 = nt_blk * TILE_N;

    const int e = sel[b * K_SEL + kk];

    const float* Abase = x + (((size_t)m0 * B_DIM + b) << 10);         // row stride B*IN
    const float* Bbase = w + ((((size_t)e << 10) + (size_t)n0) << 10); // row stride IN

    const uint32_t smem_base = smem_u32(smem);

    if (wid >= 8) {
        // ====================== PRODUCER (warps 8-11) =======================
        const int pid = tid - 256;             // 0..127
        int s = 0;
        for (int c = 0; c < NCHUNK; ++c) {
            if (c >= NSTG) BAR_SYNC(5 + s);    // wait stage empty

            const int kbase = c * KC;
            char* st = smem + s * STAGE_BYTES;

            // A: 128 rows x 64 el = 1024 octs -> 8/thread
            #pragma unroll
            for (int p = 0; p < 8; ++p) {
                int g = pid + p * 128;
                int row = g >> 3, oct = g & 7;
                const float* src =
                    Abase + (size_t)row * (B_DIM * IN_DIM) + kbase + oct * 8;
                uint4 v0 = *reinterpret_cast<const uint4*>(src);
                uint4 v1 = *reinterpret_cast<const uint4*>(src + 4);
                uint4 hv = cvt_oct_f16(v0, v1);
                uint32_t sw = sw128((uint32_t)(row * 128 + oct * 16));
                *reinterpret_cast<uint4*>(st + OFF_AH + sw) = hv;
            }
            // B: 128 rows x 64 el = 1024 octs -> 8/thread
            #pragma unroll
            for (int p = 0; p < 8; ++p) {
                int g = pid + p * 128;
                int row = g >> 3, oct = g & 7;
                const float* src =
                    Bbase + (size_t)row * IN_DIM + kbase + oct * 8;
                uint4 v0 = *reinterpret_cast<const uint4*>(src);
                uint4 v1 = *reinterpret_cast<const uint4*>(src + 4);
                uint4 hv = cvt_oct_f16(v0, v1);
                uint32_t sw = sw128((uint32_t)(row * 128 + oct * 16));
                *reinterpret_cast<uint4*>(st + OFF_BH + sw) = hv;
            }
            BAR_ARRIVE(1 + s);                 // stage full
            if (++s == NSTG) s = 0;
        }
        return;
    }

    // ======================== CONSUMER (warps 0-7) ==========================
    // 4 (m) x 2 (n) warp layout; warp tile 32 x 64 (proven geometry)
    const int warp_m = (wid & 3) * 32;
    const int warp_n = (wid >> 2) * 64;
    const int tile = lid >> 3;                 // ldmatrix sub-tile 0..3
    const int trow = lid & 7;
    const int qr = lid >> 2;                   // mma fragment row
    const int qc = lid & 3;

    // ldsm base offsets; k16 variant = base ^ (k16<<5).
    // Identity: sw128(row*128+kb) = row*128 + (kb ^ ((row&7)<<4)) for kb<128.
    uint32_t aBase[2], bBase[4];
    #pragma unroll
    for (int mt = 0; mt < 2; ++mt) {
        int row  = warp_m + mt * 16 + ((tile & 1) << 3) + trow;
        int tsel = (tile >> 1) << 4;
        aBase[mt] = (uint32_t)(row * 128 + (tsel ^ ((row & 7) << 4)));
    }
    #pragma unroll
    for (int nt2 = 0; nt2 < 4; ++nt2) {
        int row  = warp_n + nt2 * 16 + ((tile >> 1) << 3) + trow;
        int tsel = (tile & 1) << 4;
        bBase[nt2] = (uint32_t)(row * 128 + (tsel ^ ((row & 7) << 4)));
    }

    float acc[2][8][4];
    #pragma unroll
    for (int i = 0; i < 2; ++i)
        #pragma unroll
        for (int j = 0; j < 8; ++j)
            #pragma unroll
            for (int v = 0; v < 4; ++v) acc[i][j][v] = 0.0f;

    int s = 0;
    for (int c = 0; c < NCHUNK; ++c) {
        BAR_SYNC(1 + s);                       // wait stage full

        const uint32_t stB = smem_base + s * STAGE_BYTES;
        const uint32_t ahB = stB + OFF_AH;
        const uint32_t bhB = stB + OFF_BH;

        #pragma unroll
        for (int k16 = 0; k16 < 4; ++k16) {
            const uint32_t kx = (uint32_t)(k16 << 5);
            uint32_t ah[2][4], bh[8][2];

            #pragma unroll
            for (int mt = 0; mt < 2; ++mt)
                ldsm4(ah[mt], ahB + (aBase[mt] ^ kx));
            #pragma unroll
            for (int nt2 = 0; nt2 < 4; ++nt2) {
                uint32_t r[4];
                ldsm4(r, bhB + (bBase[nt2] ^ kx));
                bh[2 * nt2][0] = r[0]; bh[2 * nt2][1] = r[1];
                bh[2 * nt2 + 1][0] = r[2]; bh[2 * nt2 + 1][1] = r[3];
            }
            // last smem read of this stage -> release early
            if (k16 == 3) BAR_ARRIVE(5 + s);
            #pragma unroll
            for (int mt = 0; mt < 2; ++mt)
                #pragma unroll
                for (int nt = 0; nt < 8; ++nt)
                    mma16816(acc[mt][nt], ah[mt], bh[nt]);
        }
        if (++s == NSTG) s = 0;
    }

    // ---- epilogue: direct fp32 stores ----
    const size_t row_stride = (size_t)B_DIM * K_SEL * OUT_DIM;   // 16384 floats
    #pragma unroll
    for (int mt = 0; mt < 2; ++mt) {
        const int t = m0 + warp_m + mt * 16 + qr;
        float* orow = out + (size_t)t * row_stride
                          + ((size_t)b * K_SEL + kk) * OUT_DIM
                          + n0 + warp_n + qc * 2;
        #pragma unroll
        for (int nt = 0; nt < 8; ++nt) {
            float2 v0 = make_float2(acc[mt][nt][0], acc[mt][nt][1]);
            float2 v1 = make_float2(acc[mt][nt][2], acc[mt][nt][3]);
            *reinterpret_cast<float2*>(orow + nt * 8) = v0;
            *reinterpret_cast<float2*>(orow + nt * 8 + 8 * row_stride) = v1;
        }
    }
}

// ============================================================================
// Launch
// ============================================================================
extern "C" void kernel_launch(void* const* d_in, const int* in_sizes, int n_in,
                              void* d_out, int out_size) {
    (void)in_sizes; (void)n_in; (void)out_size;
    const float* x   = (const float*)d_in[0];
    const int*   sel = (const int*)d_in[1];
    const float* w   = (const float*)d_in[2];
    float*       out = (float*)d_out;

    cudaFuncSetAttribute(modlin_kernel,
                         cudaFuncAttributeMaxDynamicSharedMemorySize, SMEM_TOTAL);

    dim3 grid(OUT_DIM / TILE_N,            // 8
              T_DIM / TILE_M,              // 16
              B_DIM * K_SEL);              // 16
    modlin_kernel<<<grid, THREADS, SMEM_TOTAL>>>(x, sel, w, out);
}

// round 16
// speedup vs baseline: 1.1461x; 1.1461x over previous
#include <cuda_runtime.h>
#include <cuda_fp16.h>
#include <cstdint>

// ============================================================================
// ModularLinear on GB300 — base-arch build. R16: single-term fp16 GEMM
// (C = fp16(a)*fp16(b), fp32 acc; rel_err ~2.8e-4 measured in R13) with a
// 64x64 warp tile (2x4 warp grid, TILE 128x256) to double MMA:LDSM density —
// the crossbar-traffic invariance result says only warp-tile area cuts smem
// traffic per MMA. 320 threads (256 consumer + 64 producer) -> 204-reg cap;
// 1-term fragments fit (~190 regs) where 3-term (R9) could not.
//
//   out[t, b, kk*1024 + o] = sum_i x[t, b, i] * w[sel[b,kk], o, i]
//   16 independent GEMMs of 2048 x 1024 x 1024 (fp32).
// ============================================================================

#define T_DIM   2048
#define B_DIM   8
#define IN_DIM  1024
#define OUT_DIM 1024
#define K_SEL   2

#define TILE_M  128
#define TILE_N  256
#define KC      64                         // K-chunk (fp32 elements)
#define NCHUNK  (IN_DIM / KC)              // 16
#define THREADS 320                        // 256 consumer + 64 producer
#define NSTG    4

// fp16 tiles: 128B rows, SW128-swizzled
#define A_TILE      (TILE_M * KC * 2)      // 16384
#define B_TILE      (TILE_N * KC * 2)      // 32768
#define OFF_AH      0
#define OFF_BH      A_TILE                 // 16384
#define STAGE_BYTES (A_TILE + B_TILE)      // 49152
#define SMEM_TOTAL  (NSTG * STAGE_BYTES)   // 196608

// ---------------------------------------------------------------------------
// PTX helpers (base-arch only)
// ---------------------------------------------------------------------------
__device__ __forceinline__ uint32_t smem_u32(const void* p) {
    uint32_t a;
    asm("{ .reg .u64 t; cvta.to.shared.u64 t, %1; cvt.u32.u64 %0, t; }"
        : "=r"(a) : "l"(p));
    return a;
}

#define BAR_SYNC(id)   asm volatile("bar.sync %0, %1;"   :: "r"(id), "n"(THREADS) : "memory")
#define BAR_ARRIVE(id) asm volatile("bar.arrive %0, %1;" :: "r"(id), "n"(THREADS) : "memory")

__device__ __forceinline__ void ldsm4(uint32_t* r, uint32_t addr) {
    asm volatile("ldmatrix.sync.aligned.m8n8.x4.shared.b16 {%0,%1,%2,%3}, [%4];"
                 : "=r"(r[0]), "=r"(r[1]), "=r"(r[2]), "=r"(r[3])
                 : "r"(addr));
}

// D += A * B  (m16n8k16, fp16 in, fp32 acc)
__device__ __forceinline__ void mma16816(float* c, const uint32_t* a,
                                         const uint32_t* b) {
    asm volatile(
        "mma.sync.aligned.m16n8k16.row.col.f32.f16.f16.f32 "
        "{%0,%1,%2,%3}, {%4,%5,%6,%7}, {%8,%9}, {%0,%1,%2,%3};"
        : "+f"(c[0]), "+f"(c[1]), "+f"(c[2]), "+f"(c[3])
        : "r"(a[0]), "r"(a[1]), "r"(a[2]), "r"(a[3]),
          "r"(b[0]), "r"(b[1]));
}

// SW128 swizzle for 128B rows: bits[6:4] ^= bits[9:7]
__device__ __forceinline__ uint32_t sw128(uint32_t bo) {
    return bo ^ ((bo >> 3) & 0x70);
}

__device__ __forceinline__ uint32_t f2h2(float a, float b) {
    __half2 h = __floats2half2_rn(a, b);
    return *reinterpret_cast<uint32_t*>(&h);
}

// convert 8 fp32 (two uint4) to packed fp16 (one uint4)
__device__ __forceinline__ uint4 cvt_oct_f16(uint4 u0, uint4 u1) {
    uint4 hi;
    hi.x = f2h2(__uint_as_float(u0.x), __uint_as_float(u0.y));
    hi.y = f2h2(__uint_as_float(u0.z), __uint_as_float(u0.w));
    hi.z = f2h2(__uint_as_float(u1.x), __uint_as_float(u1.y));
    hi.w = f2h2(__uint_as_float(u1.z), __uint_as_float(u1.w));
    return hi;
}

// ============================================================================
// Kernel
// ============================================================================
__global__ void __launch_bounds__(THREADS, 1)
modlin_kernel(const float* __restrict__ x, const int* __restrict__ sel,
              const float* __restrict__ w, float* __restrict__ out)
{
    extern __shared__ char smem[];
    const int tid = threadIdx.x;
    const int wid = tid >> 5;
    const int lid = tid & 31;

    const int nt_blk = blockIdx.x;            // 0..3
    const int mt_blk = blockIdx.y;            // 0..15
    const int pi     = blockIdx.z;            // 0..15  (b,k) pair
    const int b  = pi >> 1;
    const int kk = pi & 1;
    const int m0 = mt_blk * TILE_M;
    const int n0 = nt_blk * TILE_N;

    const int e = sel[b * K_SEL + kk];

    const float* Abase = x + (((size_t)m0 * B_DIM + b) << 10);         // row stride B*IN
    const float* Bbase = w + ((((size_t)e << 10) + (size_t)n0) << 10); // row stride IN

    const uint32_t smem_base = smem_u32(smem);

    if (wid >= 8) {
        // ====================== PRODUCER (warps 8-9) ========================
        const int pid = tid - 256;             // 0..63
        int s = 0;
        for (int c = 0; c < NCHUNK; ++c) {
            if (c >= NSTG) BAR_SYNC(5 + s);    // wait stage empty

            const int kbase = c * KC;
            char* st = smem + s * STAGE_BYTES;

            // A: 128 rows x 64 el = 1024 octs -> 16/thread (2 batches of 8)
            #pragma unroll
            for (int batch = 0; batch < 2; ++batch) {
                uint4 v[16];
                #pragma unroll
                for (int p = 0; p < 8; ++p) {
                    int g = pid + (batch * 8 + p) * 64;
                    int row = g >> 3, oct = g & 7;
                    const float* src =
                        Abase + (size_t)row * (B_DIM * IN_DIM) + kbase + oct * 8;
                    v[2 * p]     = *reinterpret_cast<const uint4*>(src);
                    v[2 * p + 1] = *reinterpret_cast<const uint4*>(src + 4);
                }
                #pragma unroll
                for (int p = 0; p < 8; ++p) {
                    int g = pid + (batch * 8 + p) * 64;
                    int row = g >> 3, oct = g & 7;
                    uint4 hv = cvt_oct_f16(v[2 * p], v[2 * p + 1]);
                    uint32_t sw = sw128((uint32_t)(row * 128 + oct * 16));
                    *reinterpret_cast<uint4*>(st + OFF_AH + sw) = hv;
                }
            }
            // B: 256 rows x 64 el = 2048 octs -> 32/thread (4 batches of 8)
            #pragma unroll
            for (int batch = 0; batch < 4; ++batch) {
                uint4 v[16];
                #pragma unroll
                for (int p = 0; p < 8; ++p) {
                    int g = pid + (batch * 8 + p) * 64;
                    int row = g >> 3, oct = g & 7;
                    const float* src =
                        Bbase + (size_t)row * IN_DIM + kbase + oct * 8;
                    v[2 * p]     = *reinterpret_cast<const uint4*>(src);
                    v[2 * p + 1] = *reinterpret_cast<const uint4*>(src + 4);
                }
                #pragma unroll
                for (int p = 0; p < 8; ++p) {
                    int g = pid + (batch * 8 + p) * 64;
                    int row = g >> 3, oct = g & 7;
                    uint4 hv = cvt_oct_f16(v[2 * p], v[2 * p + 1]);
                    uint32_t sw = sw128((uint32_t)(row * 128 + oct * 16));
                    *reinterpret_cast<uint4*>(st + OFF_BH + sw) = hv;
                }
            }
            BAR_ARRIVE(1 + s);                 // stage full
            if (++s == NSTG) s = 0;
        }
        return;
    }

    // ======================== CONSUMER (warps 0-7) ==========================
    // 2 (m) x 4 (n) warp layout; warp tile 64 x 64
    const int warp_m = (wid & 1) * 64;
    const int warp_n = (wid >> 1) * 64;
    const int tile = lid >> 3;                 // ldmatrix sub-tile 0..3
    const int trow = lid & 7;
    const int qr = lid >> 2;                   // mma fragment row
    const int qc = lid & 3;

    // ldsm base offsets; k16 variant = base ^ (k16<<5).
    // Identity (validated R12/R13): sw128(r*128+kb) = r*128 + (kb ^ ((r&7)<<4))
    uint32_t aBase[4], bBase[4];
    #pragma unroll
    for (int mt = 0; mt < 4; ++mt) {
        int row  = warp_m + mt * 16 + ((tile & 1) << 3) + trow;
        int tsel = (tile >> 1) << 4;
        aBase[mt] = (uint32_t)(row * 128 + (tsel ^ ((row & 7) << 4)));
    }
    #pragma unroll
    for (int nt2 = 0; nt2 < 4; ++nt2) {
        int row  = warp_n + nt2 * 16 + ((tile >> 1) << 3) + trow;
        int tsel = (tile & 1) << 4;
        bBase[nt2] = (uint32_t)(row * 128 + (tsel ^ ((row & 7) << 4)));
    }

    float acc[4][8][4];
    #pragma unroll
    for (int i = 0; i < 4; ++i)
        #pragma unroll
        for (int j = 0; j < 8; ++j)
            #pragma unroll
            for (int v = 0; v < 4; ++v) acc[i][j][v] = 0.0f;

    int s = 0;
    for (int c = 0; c < NCHUNK; ++c) {
        BAR_SYNC(1 + s);                       // wait stage full

        const uint32_t stB = smem_base + s * STAGE_BYTES;
        const uint32_t ahB = stB + OFF_AH;
        const uint32_t bhB = stB + OFF_BH;

        #pragma unroll
        for (int k16 = 0; k16 < 4; ++k16) {
            const uint32_t kx = (uint32_t)(k16 << 5);
            uint32_t ah[4][4], bh[8][2];

            #pragma unroll
            for (int mt = 0; mt < 4; ++mt)
                ldsm4(ah[mt], ahB + (aBase[mt] ^ kx));
            #pragma unroll
            for (int nt2 = 0; nt2 < 4; ++nt2) {
                uint32_t r[4];
                ldsm4(r, bhB + (bBase[nt2] ^ kx));
                bh[2 * nt2][0] = r[0]; bh[2 * nt2][1] = r[1];
                bh[2 * nt2 + 1][0] = r[2]; bh[2 * nt2 + 1][1] = r[3];
            }
            // last smem read of this stage -> release early
            if (k16 == 3) BAR_ARRIVE(5 + s);
            // 32 independent MMAs
            #pragma unroll
            for (int mt = 0; mt < 4; ++mt)
                #pragma unroll
                for (int nt = 0; nt < 8; ++nt)
                    mma16816(acc[mt][nt], ah[mt], bh[nt]);
        }
        if (++s == NSTG) s = 0;
    }

    // ---- epilogue: direct fp32 stores ----
    const size_t row_stride = (size_t)B_DIM * K_SEL * OUT_DIM;   // 16384 floats
    #pragma unroll
    for (int mt = 0; mt < 4; ++mt) {
        const int t = m0 + warp_m + mt * 16 + qr;
        float* orow = out + (size_t)t * row_stride
                          + ((size_t)b * K_SEL + kk) * OUT_DIM
                          + n0 + warp_n + qc * 2;
        #pragma unroll
        for (int nt = 0; nt < 8; ++nt) {
            float2 v0 = make_float2(acc[mt][nt][0], acc[mt][nt][1]);
            float2 v1 = make_float2(acc[mt][nt][2], acc[mt][nt][3]);
            *reinterpret_cast<float2*>(orow + nt * 8) = v0;
            *reinterpret_cast<float2*>(orow + nt * 8 + 8 * row_stride) = v1;
        }
    }
}

// ============================================================================
// Launch
// ============================================================================
extern "C" void kernel_launch(void* const* d_in, const int* in_sizes, int n_in,
                              void* d_out, int out_size) {
    (void)in_sizes; (void)n_in; (void)out_size;
    const float* x   = (const float*)d_in[0];
    const int*   sel = (const int*)d_in[1];
    const float* w   = (const float*)d_in[2];
    float*       out = (float*)d_out;

    cudaFuncSetAttribute(modlin_kernel,
                         cudaFuncAttributeMaxDynamicSharedMemorySize, SMEM_TOTAL);

    dim3 grid(OUT_DIM / TILE_N,            // 4
              T_DIM / TILE_M,              // 16
              B_DIM * K_SEL);              // 16
    modlin_kernel<<<grid, THREADS, SMEM_TOTAL>>>(x, sel, w, out);
}

// round 17
// speedup vs baseline: 1.8505x; 1.6147x over previous
#include <cuda_runtime.h>
#include <cuda_fp16.h>
#include <cstdint>

// ============================================================================
// ModularLinear on GB300 — base-arch build. R17 = R16 (TILE 128x256, 64x64
// warp tile, 1-term fp16: C = fp16(a)*fp16(b), rel_err 2.78e-4) with the
// producer restored to 4 warps (THREADS 320 -> 384). R16 showed tensor-busy
// == the 1-term floor but issue=11.8%: 2 producer warps (48 LDG.128/thread/
// chunk) were the critical path. 384 x 168 regs = 64512 <= 64K RF (R16
// measured 168 regs for this consumer), so 4 producer warps now fit.
//
//   out[t, b, kk*1024 + o] = sum_i x[t, b, i] * w[sel[b,kk], o, i]
//   16 independent GEMMs of 2048 x 1024 x 1024 (fp32).
// ============================================================================

#define T_DIM   2048
#define B_DIM   8
#define IN_DIM  1024
#define OUT_DIM 1024
#define K_SEL   2

#define TILE_M  128
#define TILE_N  256
#define KC      64                         // K-chunk (fp32 elements)
#define NCHUNK  (IN_DIM / KC)              // 16
#define THREADS 384                        // 256 consumer + 128 producer
#define NSTG    4

// fp16 tiles: 128B rows, SW128-swizzled
#define A_TILE      (TILE_M * KC * 2)      // 16384
#define B_TILE      (TILE_N * KC * 2)      // 32768
#define OFF_AH      0
#define OFF_BH      A_TILE                 // 16384
#define STAGE_BYTES (A_TILE + B_TILE)      // 49152
#define SMEM_TOTAL  (NSTG * STAGE_BYTES)   // 196608

// ---------------------------------------------------------------------------
// PTX helpers (base-arch only)
// ---------------------------------------------------------------------------
__device__ __forceinline__ uint32_t smem_u32(const void* p) {
    uint32_t a;
    asm("{ .reg .u64 t; cvta.to.shared.u64 t, %1; cvt.u32.u64 %0, t; }"
        : "=r"(a) : "l"(p));
    return a;
}

#define BAR_SYNC(id)   asm volatile("bar.sync %0, %1;"   :: "r"(id), "n"(THREADS) : "memory")
#define BAR_ARRIVE(id) asm volatile("bar.arrive %0, %1;" :: "r"(id), "n"(THREADS) : "memory")

__device__ __forceinline__ void ldsm4(uint32_t* r, uint32_t addr) {
    asm volatile("ldmatrix.sync.aligned.m8n8.x4.shared.b16 {%0,%1,%2,%3}, [%4];"
                 : "=r"(r[0]), "=r"(r[1]), "=r"(r[2]), "=r"(r[3])
                 : "r"(addr));
}

// D += A * B  (m16n8k16, fp16 in, fp32 acc)
__device__ __forceinline__ void mma16816(float* c, const uint32_t* a,
                                         const uint32_t* b) {
    asm volatile(
        "mma.sync.aligned.m16n8k16.row.col.f32.f16.f16.f32 "
        "{%0,%1,%2,%3}, {%4,%5,%6,%7}, {%8,%9}, {%0,%1,%2,%3};"
        : "+f"(c[0]), "+f"(c[1]), "+f"(c[2]), "+f"(c[3])
        : "r"(a[0]), "r"(a[1]), "r"(a[2]), "r"(a[3]),
          "r"(b[0]), "r"(b[1]));
}

// SW128 swizzle for 128B rows: bits[6:4] ^= bits[9:7]
__device__ __forceinline__ uint32_t sw128(uint32_t bo) {
    return bo ^ ((bo >> 3) & 0x70);
}

__device__ __forceinline__ uint32_t f2h2(float a, float b) {
    __half2 h = __floats2half2_rn(a, b);
    return *reinterpret_cast<uint32_t*>(&h);
}

// convert 8 fp32 (two uint4) to packed fp16 (one uint4)
__device__ __forceinline__ uint4 cvt_oct_f16(uint4 u0, uint4 u1) {
    uint4 hi;
    hi.x = f2h2(__uint_as_float(u0.x), __uint_as_float(u0.y));
    hi.y = f2h2(__uint_as_float(u0.z), __uint_as_float(u0.w));
    hi.z = f2h2(__uint_as_float(u1.x), __uint_as_float(u1.y));
    hi.w = f2h2(__uint_as_float(u1.z), __uint_as_float(u1.w));
    return hi;
}

// ============================================================================
// Kernel
// ============================================================================
__global__ void __launch_bounds__(THREADS, 1)
modlin_kernel(const float* __restrict__ x, const int* __restrict__ sel,
              const float* __restrict__ w, float* __restrict__ out)
{
    extern __shared__ char smem[];
    const int tid = threadIdx.x;
    const int wid = tid >> 5;
    const int lid = tid & 31;

    const int nt_blk = blockIdx.x;            // 0..3
    const int mt_blk = blockIdx.y;            // 0..15
    const int pi     = blockIdx.z;            // 0..15  (b,k) pair
    const int b  = pi >> 1;
    const int kk = pi & 1;
    const int m0 = mt_blk * TILE_M;
    const int n0 = nt_blk * TILE_N;

    const int e = sel[b * K_SEL + kk];

    const float* Abase = x + (((size_t)m0 * B_DIM + b) << 10);         // row stride B*IN
    const float* Bbase = w + ((((size_t)e << 10) + (size_t)n0) << 10); // row stride IN

    const uint32_t smem_base = smem_u32(smem);

    if (wid >= 8) {
        // ====================== PRODUCER (warps 8-11) =======================
        const int pid = tid - 256;             // 0..127
        int s = 0;
        for (int c = 0; c < NCHUNK; ++c) {
            if (c >= NSTG) BAR_SYNC(5 + s);    // wait stage empty

            const int kbase = c * KC;
            char* st = smem + s * STAGE_BYTES;

            // A: 128 rows x 64 el = 1024 octs -> 8/thread (1 batch)
            {
                uint4 v[16];
                #pragma unroll
                for (int p = 0; p < 8; ++p) {
                    int g = pid + p * 128;
                    int row = g >> 3, oct = g & 7;
                    const float* src =
                        Abase + (size_t)row * (B_DIM * IN_DIM) + kbase + oct * 8;
                    v[2 * p]     = *reinterpret_cast<const uint4*>(src);
                    v[2 * p + 1] = *reinterpret_cast<const uint4*>(src + 4);
                }
                #pragma unroll
                for (int p = 0; p < 8; ++p) {
                    int g = pid + p * 128;
                    int row = g >> 3, oct = g & 7;
                    uint4 hv = cvt_oct_f16(v[2 * p], v[2 * p + 1]);
                    uint32_t sw = sw128((uint32_t)(row * 128 + oct * 16));
                    *reinterpret_cast<uint4*>(st + OFF_AH + sw) = hv;
                }
            }
            // B: 256 rows x 64 el = 2048 octs -> 16/thread (2 batches of 8)
            #pragma unroll
            for (int batch = 0; batch < 2; ++batch) {
                uint4 v[16];
                #pragma unroll
                for (int p = 0; p < 8; ++p) {
                    int g = pid + (batch * 8 + p) * 128;
                    int row = g >> 3, oct = g & 7;
                    const float* src =
                        Bbase + (size_t)row * IN_DIM + kbase + oct * 8;
                    v[2 * p]     = *reinterpret_cast<const uint4*>(src);
                    v[2 * p + 1] = *reinterpret_cast<const uint4*>(src + 4);
                }
                #pragma unroll
                for (int p = 0; p < 8; ++p) {
                    int g = pid + (batch * 8 + p) * 128;
                    int row = g >> 3, oct = g & 7;
                    uint4 hv = cvt_oct_f16(v[2 * p], v[2 * p + 1]);
                    uint32_t sw = sw128((uint32_t)(row * 128 + oct * 16));
                    *reinterpret_cast<uint4*>(st + OFF_BH + sw) = hv;
                }
            }
            BAR_ARRIVE(1 + s);                 // stage full
            if (++s == NSTG) s = 0;
        }
        return;
    }

    // ======================== CONSUMER (warps 0-7) ==========================
    // 2 (m) x 4 (n) warp layout; warp tile 64 x 64
    const int warp_m = (wid & 1) * 64;
    const int warp_n = (wid >> 1) * 64;
    const int tile = lid >> 3;                 // ldmatrix sub-tile 0..3
    const int trow = lid & 7;
    const int qr = lid >> 2;                   // mma fragment row
    const int qc = lid & 3;

    // ldsm base offsets; k16 variant = base ^ (k16<<5).
    // Identity (validated R12/R13/R16): sw128(r*128+kb) = r*128 + (kb^((r&7)<<4))
    uint32_t aBase[4], bBase[4];
    #pragma unroll
    for (int mt = 0; mt < 4; ++mt) {
        int row  = warp_m + mt * 16 + ((tile & 1) << 3) + trow;
        int tsel = (tile >> 1) << 4;
        aBase[mt] = (uint32_t)(row * 128 + (tsel ^ ((row & 7) << 4)));
    }
    #pragma unroll
    for (int nt2 = 0; nt2 < 4; ++nt2) {
        int row  = warp_n + nt2 * 16 + ((tile >> 1) << 3) + trow;
        int tsel = (tile & 1) << 4;
        bBase[nt2] = (uint32_t)(row * 128 + (tsel ^ ((row & 7) << 4)));
    }

    float acc[4][8][4];
    #pragma unroll
    for (int i = 0; i < 4; ++i)
        #pragma unroll
        for (int j = 0; j < 8; ++j)
            #pragma unroll
            for (int v = 0; v < 4; ++v) acc[i][j][v] = 0.0f;

    int s = 0;
    for (int c = 0; c < NCHUNK; ++c) {
        BAR_SYNC(1 + s);                       // wait stage full

        const uint32_t stB = smem_base + s * STAGE_BYTES;
        const uint32_t ahB = stB + OFF_AH;
        const uint32_t bhB = stB + OFF_BH;

        #pragma unroll
        for (int k16 = 0; k16 < 4; ++k16) {
            const uint32_t kx = (uint32_t)(k16 << 5);
            uint32_t ah[4][4], bh[8][2];

            #pragma unroll
            for (int mt = 0; mt < 4; ++mt)
                ldsm4(ah[mt], ahB + (aBase[mt] ^ kx));
            #pragma unroll
            for (int nt2 = 0; nt2 < 4; ++nt2) {
                uint32_t r[4];
                ldsm4(r, bhB + (bBase[nt2] ^ kx));
                bh[2 * nt2][0] = r[0]; bh[2 * nt2][1] = r[1];
                bh[2 * nt2 + 1][0] = r[2]; bh[2 * nt2 + 1][1] = r[3];
            }
            // last smem read of this stage -> release early
            if (k16 == 3) BAR_ARRIVE(5 + s);
            // 32 independent MMAs per phase
            #pragma unroll
            for (int mt = 0; mt < 4; ++mt)
                #pragma unroll
                for (int nt = 0; nt < 8; ++nt)
                    mma16816(acc[mt][nt], ah[mt], bh[nt]);
        }
        if (++s == NSTG) s = 0;
    }

    // ---- epilogue: direct fp32 stores ----
    const size_t row_stride = (size_t)B_DIM * K_SEL * OUT_DIM;   // 16384 floats
    #pragma unroll
    for (int mt = 0; mt < 4; ++mt) {
        const int t = m0 + warp_m + mt * 16 + qr;
        float* orow = out + (size_t)t * row_stride
                          + ((size_t)b * K_SEL + kk) * OUT_DIM
                          + n0 + warp_n + qc * 2;
        #pragma unroll
        for (int nt = 0; nt < 8; ++nt) {
            float2 v0 = make_float2(acc[mt][nt][0], acc[mt][nt][1]);
            float2 v1 = make_float2(acc[mt][nt][2], acc[mt][nt][3]);
            *reinterpret_cast<float2*>(orow + nt * 8) = v0;
            *reinterpret_cast<float2*>(orow + nt * 8 + 8 * row_stride) = v1;
        }
    }
}

// ============================================================================
// Launch
// ============================================================================
extern "C" void kernel_launch(void* const* d_in, const int* in_sizes, int n_in,
                              void* d_out, int out_size) {
    (void)in_sizes; (void)n_in; (void)out_size;
    const float* x   = (const float*)d_in[0];
    const int*   sel = (const int*)d_in[1];
    const float* w   = (const float*)d_in[2];
    float*       out = (float*)d_out;

    cudaFuncSetAttribute(modlin_kernel,
                         cudaFuncAttributeMaxDynamicSharedMemorySize, SMEM_TOTAL);

    dim3 grid(OUT_DIM / TILE_N,            // 4
              T_DIM / TILE_M,              // 16
              B_DIM * K_SEL);              // 16
    modlin_kernel<<<grid, THREADS, SMEM_TOTAL>>>(x, sel, w, out);
}